// round 2
// baseline (speedup 1.0000x reference)
#include <cuda_runtime.h>

// VectorQuantizer: N=262144 points (D=64), K=1024 codes.
// out = [ z_q (N*64 floats) | encoding_inds as float (N) ]
//
// Round 2: natural f32x2 packing. z kept as (z_i, z_{i+1}) b64 pairs (64 regs
// per point), codebook row-major in SMEM. fma.rn.f32x2 accumulates even/odd
// partial dots for ONE code; each thread processes 2 points so every LDS.128
// of codebook feeds 4 fma2 (2 per point) -> 8 LDS per code*point (was 16).
// Final score keeps the reference's exact rounding:
//   dist2 = fl( fl(zsq - 2*dot) + cb_sq ), strict-< argmin (first index wins).

#define KCODES 1024
#define DIM    64
#define CHUNK  512   // codes per SMEM stage (2 stages)
#define TPB    256
#define PTS    2     // points per thread

#define SMEM_FLOATS (CHUNK * DIM + CHUNK)
#define SMEM_BYTES  (SMEM_FLOATS * 4)     // 133120 B

typedef unsigned long long u64;

__device__ float g_cbsq[KCODES];

static __device__ __forceinline__ void unpack2(u64 v, float& lo, float& hi) {
    unsigned int a, b;
    asm("mov.b64 {%0, %1}, %2;" : "=r"(a), "=r"(b) : "l"(v));
    lo = __uint_as_float(a);
    hi = __uint_as_float(b);
}
static __device__ __forceinline__ u64 fma2(u64 a, u64 b, u64 c) {
    u64 d;
    asm("fma.rn.f32x2 %0, %1, %2, %3;" : "=l"(d) : "l"(a), "l"(b), "l"(c));
    return d;
}
static __device__ __forceinline__ u64 add2(u64 a, u64 b) {
    u64 d;
    asm("add.rn.f32x2 %0, %1, %2;" : "=l"(d) : "l"(a), "l"(b));
    return d;
}

// ---------------------------------------------------------------------------
// cb_sq[k] = sequential fp32 sum of squares of codebook row k.
__global__ void cbsq_kernel(const float* __restrict__ cb) {
    int k = blockIdx.x * blockDim.x + threadIdx.x;
    if (k < KCODES) {
        const float* r = cb + (size_t)k * DIM;
        float s = 0.f;
#pragma unroll
        for (int i = 0; i < DIM; i++)
            s = __fadd_rn(s, __fmul_rn(r[i], r[i]));
        g_cbsq[k] = s;
    }
}

// ---------------------------------------------------------------------------
__global__ __launch_bounds__(TPB, 1)
void vq_kernel(const float* __restrict__ z_e,
               const float* __restrict__ cb,
               float* __restrict__ out,
               int N) {
    extern __shared__ float smem[];
    float* s_cb  = smem;                 // CHUNK*DIM floats, natural row-major
    float* s_csq = smem + CHUNK * DIM;   // CHUNK floats

    const int base = blockIdx.x * (PTS * TPB);
    const int n0 = base + threadIdx.x;
    const int n1 = n0 + TPB;
    const bool actA = (n0 < N);
    const bool actB = (n1 < N);

    // z packed naturally: zX[j] = (z[2j], z[2j+1]) as b64. zsq sequential fp32.
    u64 zA[DIM / 2], zB[DIM / 2];
    float zsqA = 0.f, zsqB = 0.f;
    if (actA) {
        const ulonglong2* zp = (const ulonglong2*)(z_e + (size_t)n0 * DIM);
#pragma unroll
        for (int j = 0; j < DIM / 4; j++) {
            ulonglong2 v = zp[j];
            zA[2 * j] = v.x; zA[2 * j + 1] = v.y;
            float a, b, c, d;
            unpack2(v.x, a, b); unpack2(v.y, c, d);
            zsqA = __fadd_rn(zsqA, __fmul_rn(a, a));
            zsqA = __fadd_rn(zsqA, __fmul_rn(b, b));
            zsqA = __fadd_rn(zsqA, __fmul_rn(c, c));
            zsqA = __fadd_rn(zsqA, __fmul_rn(d, d));
        }
    } else {
#pragma unroll
        for (int j = 0; j < DIM / 2; j++) zA[j] = 0ull;
    }
    if (actB) {
        const ulonglong2* zp = (const ulonglong2*)(z_e + (size_t)n1 * DIM);
#pragma unroll
        for (int j = 0; j < DIM / 4; j++) {
            ulonglong2 v = zp[j];
            zB[2 * j] = v.x; zB[2 * j + 1] = v.y;
            float a, b, c, d;
            unpack2(v.x, a, b); unpack2(v.y, c, d);
            zsqB = __fadd_rn(zsqB, __fmul_rn(a, a));
            zsqB = __fadd_rn(zsqB, __fmul_rn(b, b));
            zsqB = __fadd_rn(zsqB, __fmul_rn(c, c));
            zsqB = __fadd_rn(zsqB, __fmul_rn(d, d));
        }
    } else {
#pragma unroll
        for (int j = 0; j < DIM / 2; j++) zB[j] = 0ull;
    }

    float bestA = 3.4e38f, bestB = 3.4e38f;
    int   idxA = 0, idxB = 0;

    for (int c0 = 0; c0 < KCODES; c0 += CHUNK) {
        __syncthreads();  // protect previous stage's SMEM reads

        // Stage codebook chunk (natural layout) + cb_sq.
        {
            const float4* src = (const float4*)(cb + (size_t)c0 * DIM);
            float4* dst = (float4*)s_cb;
            for (int e = threadIdx.x; e < CHUNK * DIM / 4; e += TPB)
                dst[e] = src[e];
            for (int e = threadIdx.x; e < CHUNK; e += TPB)
                s_csq[e] = g_cbsq[c0 + e];
        }
        __syncthreads();

#pragma unroll 1
        for (int k = 0; k < CHUNK; ++k) {
            const ulonglong2* row = (const ulonglong2*)(s_cb + (k << 6));
            u64 a0 = 0ull, a1 = 0ull, b0 = 0ull, b1 = 0ull;
#pragma unroll
            for (int i = 0; i < 16; i++) {
                ulonglong2 c = row[i];
                a0 = fma2(zA[2 * i],     c.x, a0);
                b0 = fma2(zB[2 * i],     c.x, b0);
                a1 = fma2(zA[2 * i + 1], c.y, a1);
                b1 = fma2(zB[2 * i + 1], c.y, b1);
            }
            float csq = s_csq[k];
            u64 sa = add2(a0, a1);
            u64 sb = add2(b0, b1);
            float lo, hi;
            unpack2(sa, lo, hi);
            float dotA = __fadd_rn(lo, hi);
            unpack2(sb, lo, hi);
            float dotB = __fadd_rn(lo, hi);

            // Exact reference rounding: fl(zsq - 2*dot) (single rounding,
            // 2*dot exact), then fl(+cb_sq).
            float dA = __fadd_rn(__fmaf_rn(-2.f, dotA, zsqA), csq);
            float dB = __fadd_rn(__fmaf_rn(-2.f, dotB, zsqB), csq);

            int kk = c0 + k;
            if (dA < bestA) { bestA = dA; idxA = kk; }
            if (dB < bestB) { bestB = dB; idxB = kk; }
        }
    }

    if (actA) {
        float4* oq = (float4*)(out + (size_t)n0 * DIM);
        const float4* qr = (const float4*)(cb + (size_t)idxA * DIM);
#pragma unroll
        for (int i = 0; i < DIM / 4; i++) oq[i] = qr[i];
        out[(size_t)N * DIM + n0] = (float)idxA;
    }
    if (actB) {
        float4* oq = (float4*)(out + (size_t)n1 * DIM);
        const float4* qr = (const float4*)(cb + (size_t)idxB * DIM);
#pragma unroll
        for (int i = 0; i < DIM / 4; i++) oq[i] = qr[i];
        out[(size_t)N * DIM + n1] = (float)idxB;
    }
}

// ---------------------------------------------------------------------------
extern "C" void kernel_launch(void* const* d_in, const int* in_sizes, int n_in,
                              void* d_out, int out_size) {
    const float* z_e = (const float*)d_in[0];
    const float* cb  = (const float*)d_in[1];
    float* out = (float*)d_out;
    const int N = in_sizes[0] / DIM;

    cbsq_kernel<<<(KCODES + 255) / 256, 256>>>(cb);

    cudaFuncSetAttribute(vq_kernel, cudaFuncAttributeMaxDynamicSharedMemorySize,
                         SMEM_BYTES);
    const int grid = (N + PTS * TPB - 1) / (PTS * TPB);
    vq_kernel<<<grid, TPB, SMEM_BYTES>>>(z_e, cb, out, N);
}